// round 8
// baseline (speedup 1.0000x reference)
#include <cuda_runtime.h>

#define L_DIM 8192
#define B_DIM 4096
#define RANK 8
#define M_SPLITS 64
#define M_CHUNK (L_DIM / M_SPLITS)   // 128
#define B4 (B_DIM / 4)               // 1024 float4 lanes
#define L_TILE 128

typedef unsigned long long u64;

__device__ __forceinline__ void fma2(u64& d, u64 a, u64 b) {
    asm("fma.rn.f32x2 %0, %1, %2, %0;" : "+l"(d) : "l"(a), "l"(b));
}
__device__ __forceinline__ u64 dup2(float v) {
    u64 r;
    asm("mov.b64 %0, {%1, %1};" : "=l"(r) : "f"(v));
    return r;
}
__device__ __forceinline__ u64 pack2(float x, float y) {
    u64 r;
    asm("mov.b64 %0, {%1, %2};" : "=l"(r) : "f"(x), "f"(y));
    return r;
}
__device__ __forceinline__ float2 unpk2(u64 a) {
    float2 f;
    asm("mov.b64 {%0, %1}, %2;" : "=f"(f.x), "=f"(f.y) : "l"(a));
    return f;
}

// T = V @ inputs -> [RANK, B]. Zero-initialized at load; re-zeroed by out_kernel
// tail each launch, so every kernel_launch call starts from T == 0.
__device__ float g_T[RANK * B_DIM];
// per-b-quadrant completion counters for out_kernel (zero-init, self-resetting)
__device__ int g_count[4];

// stage 1: g_T[r, b] += sum_{m in chunk s} V[r, m] * inputs[m, b]  (RED.F32)
// grid: (B4/256 = 4, M_SPLITS = 64), block: 256, 2 CTAs/SM
__global__ __launch_bounds__(256, 2) void vx_kernel(
    const float* __restrict__ inp, const float* __restrict__ V) {
    __shared__ u64 Vs[RANK][M_CHUNK];   // duplicated pairs, 8 KB

    const int s = blockIdx.y;
    const int m0 = s * M_CHUNK;
    for (int i = threadIdx.x; i < RANK * M_CHUNK; i += blockDim.x) {
        int r = i >> 7;               // / M_CHUNK
        int mi = i & (M_CHUNK - 1);
        Vs[r][mi] = dup2(V[r * L_DIM + m0 + mi]);
    }
    __syncthreads();

    const int b4 = blockIdx.x * blockDim.x + threadIdx.x;  // 0..1023
    const double2* in2 = (const double2*)inp;   // float4 as 2x u64 halves

    u64 acc[RANK][2];
    #pragma unroll
    for (int r = 0; r < RANK; r++) { acc[r][0] = 0ull; acc[r][1] = 0ull; }

    #pragma unroll 8
    for (int mi = 0; mi < M_CHUNK; mi++) {
        double2 x = __ldcs(&in2[(size_t)(m0 + mi) * B4 + b4]);
        u64 xlo = (u64)__double_as_longlong(x.x);
        u64 xhi = (u64)__double_as_longlong(x.y);
        #pragma unroll
        for (int r = 0; r < RANK; r++) {
            u64 v2 = Vs[r][mi];
            fma2(acc[r][0], v2, xlo);
            fma2(acc[r][1], v2, xhi);
        }
    }

    const int b = b4 * 4;
    #pragma unroll
    for (int r = 0; r < RANK; r++) {
        float2 lo = unpk2(acc[r][0]);
        float2 hi = unpk2(acc[r][1]);
        float* dst = &g_T[r * B_DIM + b];
        atomicAdd(dst + 0, lo.x);
        atomicAdd(dst + 1, lo.y);
        atomicAdd(dst + 2, hi.x);
        atomicAdd(dst + 3, hi.y);
    }
}

// stage 2: out[l, b] = sum_r U[r, l] * T[r, b]; tail re-zeroes T for next launch
// grid: (B4/256 = 4, L_DIM / L_TILE = 64), block: 256, 2 CTAs/SM (no spill)
__global__ __launch_bounds__(256, 2) void out_kernel(
    const float* __restrict__ U, float* __restrict__ out) {
    __shared__ __align__(16) u64 Us[L_TILE][RANK];  // transposed, dup pairs, 8 KB
    __shared__ int s_last;

    const int t = threadIdx.x;
    const int l0 = blockIdx.y * L_TILE;
    for (int i = t; i < RANK * L_TILE; i += blockDim.x) {
        int li = i >> 3;
        int r = i & 7;
        Us[li][r] = dup2(U[r * L_DIM + l0 + li]);
    }
    __syncthreads();

    const int b4 = blockIdx.x * blockDim.x + t;  // 0..1023
    const float4* T4 = (const float4*)g_T;

    u64 tld[RANK][2];
    #pragma unroll
    for (int r = 0; r < RANK; r++) {
        float4 v = __ldg(&T4[r * B4 + b4]);
        tld[r][0] = pack2(v.x, v.y);
        tld[r][1] = pack2(v.z, v.w);
    }

    float4* out4 = (float4*)out;
    #pragma unroll 4
    for (int li = 0; li < L_TILE; li++) {
        // 4x LDS.128 (broadcast) for the 8 rank operands of this li
        const ulonglong2* up = (const ulonglong2*)&Us[li][0];
        ulonglong2 u01 = up[0], u23 = up[1], u45 = up[2], u67 = up[3];
        u64 a0 = 0ull, a1 = 0ull;
        fma2(a0, u01.x, tld[0][0]); fma2(a1, u01.x, tld[0][1]);
        fma2(a0, u01.y, tld[1][0]); fma2(a1, u01.y, tld[1][1]);
        fma2(a0, u23.x, tld[2][0]); fma2(a1, u23.x, tld[2][1]);
        fma2(a0, u23.y, tld[3][0]); fma2(a1, u23.y, tld[3][1]);
        fma2(a0, u45.x, tld[4][0]); fma2(a1, u45.x, tld[4][1]);
        fma2(a0, u45.y, tld[5][0]); fma2(a1, u45.y, tld[5][1]);
        fma2(a0, u67.x, tld[6][0]); fma2(a1, u67.x, tld[6][1]);
        fma2(a0, u67.y, tld[7][0]); fma2(a1, u67.y, tld[7][1]);
        float2 lo = unpk2(a0);
        float2 hi = unpk2(a1);
        __stcs(&out4[(size_t)(l0 + li) * B4 + b4],
               make_float4(lo.x, lo.y, hi.x, hi.y));
    }

    // --- tail: last CTA of this b-quadrant re-zeroes its T slice + counter ---
    __syncthreads();
    __threadfence();
    if (t == 0) {
        int old = atomicAdd(&g_count[blockIdx.x], 1);
        s_last = (old == (int)gridDim.y - 1);
    }
    __syncthreads();
    if (s_last) {
        float4 z = make_float4(0.f, 0.f, 0.f, 0.f);
        float4* Tz = (float4*)g_T;
        #pragma unroll
        for (int r = 0; r < RANK; r++)
            Tz[r * B4 + b4] = z;
        __threadfence();
        if (t == 0) atomicExch(&g_count[blockIdx.x], 0);
    }
}

extern "C" void kernel_launch(void* const* d_in, const int* in_sizes, int n_in,
                              void* d_out, int out_size) {
    const float* inp = (const float*)d_in[0];  // [L, B]
    const float* U   = (const float*)d_in[1];  // [RANK, L]
    const float* V   = (const float*)d_in[2];  // [RANK, L]
    float* out = (float*)d_out;                // [L, B]

    dim3 g1(B4 / 256, M_SPLITS);
    vx_kernel<<<g1, 256>>>(inp, V);

    dim3 g2(B4 / 256, L_DIM / L_TILE);
    out_kernel<<<g2, 256>>>(U, out);
}

// round 9
// speedup vs baseline: 1.0099x; 1.0099x over previous
#include <cuda_runtime.h>

#define L_DIM 8192
#define B_DIM 4096
#define RANK 8
#define M_SPLITS 64
#define M_CHUNK (L_DIM / M_SPLITS)   // 128
#define B4 (B_DIM / 4)               // 1024 float4 lanes
#define L_TILE 128

typedef unsigned long long u64;

__device__ __forceinline__ void fma2(u64& d, u64 a, u64 b) {
    asm("fma.rn.f32x2 %0, %1, %2, %0;" : "+l"(d) : "l"(a), "l"(b));
}
__device__ __forceinline__ u64 dup2(float v) {
    u64 r;
    asm("mov.b64 %0, {%1, %1};" : "=l"(r) : "f"(v));
    return r;
}
__device__ __forceinline__ u64 pack2(float x, float y) {
    u64 r;
    asm("mov.b64 %0, {%1, %2};" : "=l"(r) : "f"(x), "f"(y));
    return r;
}
__device__ __forceinline__ float2 unpk2(u64 a) {
    float2 f;
    asm("mov.b64 {%0, %1}, %2;" : "=f"(f.x), "=f"(f.y) : "l"(a));
    return f;
}

// T = V @ inputs -> [RANK, B]. Zero-initialized at load; re-zeroed by out_kernel
// tail each launch, so every kernel_launch call starts from T == 0.
__device__ float g_T[RANK * B_DIM];
// per-b-quadrant completion counters for out_kernel (zero-init, self-resetting)
__device__ int g_count[4];

// stage 1: g_T[r, b] += sum_{m in chunk s} V[r, m] * inputs[m, b]  (RED.F32)
// grid: (B4/256 = 4, M_SPLITS = 64), block: 256, 2 CTAs/SM
__global__ __launch_bounds__(256, 2) void vx_kernel(
    const float* __restrict__ inp, const float* __restrict__ V) {
    __shared__ u64 Vs[RANK][M_CHUNK];   // duplicated pairs, 8 KB

    const int s = blockIdx.y;
    const int m0 = s * M_CHUNK;
    for (int i = threadIdx.x; i < RANK * M_CHUNK; i += blockDim.x) {
        int r = i >> 7;               // / M_CHUNK
        int mi = i & (M_CHUNK - 1);
        Vs[r][mi] = dup2(V[r * L_DIM + m0 + mi]);
    }
    __syncthreads();

    const int b4 = blockIdx.x * blockDim.x + threadIdx.x;  // 0..1023
    const double2* in2 = (const double2*)inp;   // float4 as 2x u64 halves

    u64 acc[RANK][2];
    #pragma unroll
    for (int r = 0; r < RANK; r++) { acc[r][0] = 0ull; acc[r][1] = 0ull; }

    #pragma unroll 8
    for (int mi = 0; mi < M_CHUNK; mi++) {
        double2 x = __ldcs(&in2[(size_t)(m0 + mi) * B4 + b4]);
        u64 xlo = (u64)__double_as_longlong(x.x);
        u64 xhi = (u64)__double_as_longlong(x.y);
        #pragma unroll
        for (int r = 0; r < RANK; r++) {
            u64 v2 = Vs[r][mi];
            fma2(acc[r][0], v2, xlo);
            fma2(acc[r][1], v2, xhi);
        }
    }

    const int b = b4 * 4;
    #pragma unroll
    for (int r = 0; r < RANK; r++) {
        float2 lo = unpk2(acc[r][0]);
        float2 hi = unpk2(acc[r][1]);
        float* dst = &g_T[r * B_DIM + b];
        atomicAdd(dst + 0, lo.x);
        atomicAdd(dst + 1, lo.y);
        atomicAdd(dst + 2, hi.x);
        atomicAdd(dst + 3, hi.y);
    }
}

// stage 2: out[l, b] = sum_r U[r, l] * T[r, b]; tail re-zeroes T for next launch
// grid: (B4/256 = 4, L_DIM / L_TILE = 64), block: 256, 2 CTAs/SM (no spill)
__global__ __launch_bounds__(256, 2) void out_kernel(
    const float* __restrict__ U, float* __restrict__ out) {
    __shared__ __align__(16) u64 Us[L_TILE][RANK];  // transposed, dup pairs, 8 KB
    __shared__ int s_last;

    const int t = threadIdx.x;
    const int l0 = blockIdx.y * L_TILE;
    for (int i = t; i < RANK * L_TILE; i += blockDim.x) {
        int li = i >> 3;
        int r = i & 7;
        Us[li][r] = dup2(U[r * L_DIM + l0 + li]);
    }
    __syncthreads();

    const int b4 = blockIdx.x * blockDim.x + t;  // 0..1023
    const float4* T4 = (const float4*)g_T;

    u64 tld[RANK][2];
    #pragma unroll
    for (int r = 0; r < RANK; r++) {
        float4 v = __ldg(&T4[r * B4 + b4]);
        tld[r][0] = pack2(v.x, v.y);
        tld[r][1] = pack2(v.z, v.w);
    }

    float4* out4 = (float4*)out;
    #pragma unroll 4
    for (int li = 0; li < L_TILE; li++) {
        // 4x LDS.128 (broadcast) for the 8 rank operands of this li
        const ulonglong2* up = (const ulonglong2*)&Us[li][0];
        ulonglong2 u01 = up[0], u23 = up[1], u45 = up[2], u67 = up[3];
        u64 a0 = 0ull, a1 = 0ull;
        fma2(a0, u01.x, tld[0][0]); fma2(a1, u01.x, tld[0][1]);
        fma2(a0, u01.y, tld[1][0]); fma2(a1, u01.y, tld[1][1]);
        fma2(a0, u23.x, tld[2][0]); fma2(a1, u23.x, tld[2][1]);
        fma2(a0, u23.y, tld[3][0]); fma2(a1, u23.y, tld[3][1]);
        fma2(a0, u45.x, tld[4][0]); fma2(a1, u45.x, tld[4][1]);
        fma2(a0, u45.y, tld[5][0]); fma2(a1, u45.y, tld[5][1]);
        fma2(a0, u67.x, tld[6][0]); fma2(a1, u67.x, tld[6][1]);
        fma2(a0, u67.y, tld[7][0]); fma2(a1, u67.y, tld[7][1]);
        float2 lo = unpk2(a0);
        float2 hi = unpk2(a1);
        __stcs(&out4[(size_t)(l0 + li) * B4 + b4],
               make_float4(lo.x, lo.y, hi.x, hi.y));
    }

    // --- tail: last CTA of this b-quadrant re-zeroes its T slice + counter ---
    __syncthreads();
    __threadfence();
    if (t == 0) {
        int old = atomicAdd(&g_count[blockIdx.x], 1);
        s_last = (old == (int)gridDim.y - 1);
    }
    __syncthreads();
    if (s_last) {
        float4 z = make_float4(0.f, 0.f, 0.f, 0.f);
        float4* Tz = (float4*)g_T;
        #pragma unroll
        for (int r = 0; r < RANK; r++)
            Tz[r * B4 + b4] = z;
        __threadfence();
        if (t == 0) atomicExch(&g_count[blockIdx.x], 0);
    }
}

extern "C" void kernel_launch(void* const* d_in, const int* in_sizes, int n_in,
                              void* d_out, int out_size) {
    const float* inp = (const float*)d_in[0];  // [L, B]
    const float* U   = (const float*)d_in[1];  // [RANK, L]
    const float* V   = (const float*)d_in[2];  // [RANK, L]
    float* out = (float*)d_out;                // [L, B]

    dim3 g1(B4 / 256, M_SPLITS);
    vx_kernel<<<g1, 256>>>(inp, V);

    dim3 g2(B4 / 256, L_DIM / L_TILE);
    out_kernel<<<g2, 256>>>(U, out);
}